// round 2
// baseline (speedup 1.0000x reference)
#include <cuda_runtime.h>
#include <math.h>

#define FEAT   64
#define EMBC   256
#define IMGSZ  1024
#define NCELLS 256
#define THRESH 0.65f
#define SCAN_GRID 2160

// ---------------- device scratch (no allocations allowed) ----------------
__device__ float d_sim[FEAT * FEAT];
__device__ float d_P[1024 * 1024];           // cropped intermediate (ph x pw)
__device__ float4 d_xtab[4096];              // per-output-x interp: {i0 (bitcast), w0, w1, 0}
__device__ unsigned long long d_minkey;      // global argmin key
__device__ unsigned long long d_cellkey[NCELLS];
__device__ int d_counter;

// ---------------- ordered-float key helpers ----------------
__device__ __forceinline__ unsigned fkey(float f) {
    unsigned u = __float_as_uint(f);
    return (u >> 31) ? ~u : (u | 0x80000000u);   // monotone: smaller float -> smaller key
}
__device__ __forceinline__ float unfkey(unsigned k) {
    return (k & 0x80000000u) ? __uint_as_float(k & 0x7FFFFFFFu) : __uint_as_float(~k);
}

// ---------------- jax.image.resize (linear, antialias=False) fp-exact taps ----------------
struct Tap { int i0; float w0, w1; };

__device__ __forceinline__ float samplef(int o, float inv) {
    return __fsub_rn(__fmul_rn(__fadd_rn((float)o, 0.5f), inv), 0.5f);
}

__device__ __forceinline__ Tap make_tap(float s, int n) {
    Tap t;
    float fs = floorf(s);
    int i0 = (int)fs;
    if (i0 < 0)            { t.i0 = 0;     t.w0 = 1.f; t.w1 = 0.f; }
    else if (i0 >= n - 1)  { t.i0 = n - 2; t.w0 = 0.f; t.w1 = 1.f; }
    else {
        float w0  = __fsub_rn(1.0f, __fsub_rn(s, fs));
        float w1  = __fsub_rn(1.0f, __fsub_rn((float)(i0 + 1), s));
        float sum = __fadd_rn(w0, w1);
        if (sum != 1.0f) { w0 = __fdiv_rn(w0, sum); w1 = __fdiv_rn(w1, sum); }
        t.i0 = i0; t.w0 = w0; t.w1 = w1;
    }
    return t;
}

// ---------------- kernel 1: sim = ref . (emb / ||emb||_c), plus state init ----------------
// 32 blocks x 128 threads = 4096 threads (one per feature pixel), unroll 16 for MLP.
__global__ void __launch_bounds__(128) k_sim(const float* __restrict__ emb,
                                             const float* __restrict__ ref) {
    int p = blockIdx.x * blockDim.x + threadIdx.x;
    if (p == 0) { d_minkey = ~0ull; d_counter = 0; }
    if (p < NCELLS) d_cellkey[p] = 0ull;

    float dot = 0.f, nrm = 0.f;
    #pragma unroll 16
    for (int c = 0; c < EMBC; c++) {
        float e = __ldg(&emb[c * (FEAT * FEAT) + p]);   // coalesced across p
        dot = fmaf(__ldg(&ref[c]), e, dot);
        nrm = fmaf(e, e, nrm);
    }
    d_sim[p] = dot / sqrtf(nrm);
}

// ---------------- kernel 2: build P (resize 64->1024, cropped to ph x pw) + x-table ----------------
__global__ void k_prep(const int* __restrict__ ori) {
    int H = ori[0], W = ori[1];
    int mx = max(H, W);
    double scale = (double)IMGSZ / (double)mx;
    int ph = (int)floor((double)H * scale + 0.5);
    int pw = (int)floor((double)W * scale + 0.5);
    float invx = (float)(1.0 / ((double)W / (double)pw));

    int idx = blockIdx.x * blockDim.x + threadIdx.x;

    if (idx < W && idx < 4096) {
        Tap t = make_tap(samplef(idx, invx), pw);
        d_xtab[idx] = make_float4(__int_as_float(t.i0), t.w0, t.w1, 0.f);
    }

    const float inv1 = 0.0625f;   // 1/16 exact (64 -> 1024)
    int tot = ph * pw;
    for (int p = idx; p < tot; p += gridDim.x * blockDim.x) {
        int yy = p / pw, xx = p - yy * pw;
        Tap ty = make_tap(samplef(yy, inv1), FEAT);
        Tap tx = make_tap(samplef(xx, inv1), FEAT);
        const float* r0 = d_sim + ty.i0 * FEAT;
        float a = r0[tx.i0],        b = r0[tx.i0 + 1];
        float c = r0[FEAT + tx.i0], d = r0[FEAT + tx.i0 + 1];
        float c0 = fmaf(ty.w1, c, __fmul_rn(ty.w0, a));
        float c1 = fmaf(ty.w1, d, __fmul_rn(ty.w0, b));
        d_P[p]   = fmaf(tx.w1, c1, __fmul_rn(tx.w0, c0));
    }
}

// ---------------- kernel 3: row-wise scan + fused finalize ----------------
// One block per output row. Per row: hoist the y-contraction cy[] into smem
// (bit-identical factoring of the bilinear), then 2 LDS + mul/fma per pixel.
__global__ void __launch_bounds__(256) k_scan(const int* __restrict__ ori,
                                              float* __restrict__ out) {
    int H = ori[0], W = ori[1];
    int mx = max(H, W);
    double scale = (double)IMGSZ / (double)mx;
    int ph = (int)floor((double)H * scale + 0.5);
    int pw = (int)floor((double)W * scale + 0.5);
    float invy = (float)(1.0 / ((double)H / (double)ph));
    float r64  = (float)(scale / 64.0);   // ratio / DOWNSIZING as fp32

    __shared__ float cy[1024];            // pw <= 1024 always
    __shared__ unsigned long long sk[256];
    __shared__ float s_key[NCELLS];
    __shared__ int s_last;

    int tid = threadIdx.x;

    float rbest = INFINITY; int rbidx = 0x7FFFFFFF;

    for (int y = blockIdx.x; y < H; y += gridDim.x) {
        Tap ty = make_tap(samplef(y, invy), ph);
        const float* __restrict__ R0 = d_P + ty.i0 * pw;
        const float* __restrict__ R1 = R0 + pw;
        float wy0 = ty.w0, wy1 = ty.w1;

        __syncthreads();   // protect cy[] from previous row's readers
        for (int i = tid; i < pw; i += blockDim.x)
            cy[i] = fmaf(wy1, __ldg(&R1[i]), __fmul_rn(wy0, __ldg(&R0[i])));
        __syncthreads();

        int gy16 = 16 * (int)floorf(__fmul_rn((float)y, r64));
        int base = y * W;

        for (int x = tid; x < W; x += blockDim.x) {
            float4 tx = d_xtab[x];
            int x0 = __float_as_int(tx.x);
            float v = fmaf(tx.z, cy[x0 + 1], __fmul_rn(tx.y, cy[x0]));

            if (v < rbest) { rbest = v; rbidx = base + x; }  // idx monotone per thread

            if (v > THRESH) {   // rare path; exact semantics preserved
                int cell = gy16 + (int)floorf(__fmul_rn((float)x, r64));
                unsigned long long ck = ((unsigned long long)fkey(v) << 32)
                                      | (unsigned)(0xFFFFFFFFu - (unsigned)(base + x));
                atomicMax(&d_cellkey[cell], ck);
            }
        }
    }

    // block reduction of the argmin key
    sk[tid] = ((unsigned long long)fkey(rbest) << 32) | (unsigned)rbidx;
    __syncthreads();
    for (int o = 128; o > 0; o >>= 1) {
        if (tid < o) sk[tid] = min(sk[tid], sk[tid + o]);
        __syncthreads();
    }
    if (tid == 0) {
        atomicMin(&d_minkey, sk[0]);
        __threadfence();
        s_last = (atomicAdd(&d_counter, 1) == gridDim.x - 1);
    }
    __syncthreads();
    if (!s_last) return;

    // ---- last block: finalize (former k_final) ----
    unsigned long long ck = atomicOr(&d_cellkey[tid], 0ull);   // coherent read
    bool valid = (ck != 0ull);
    float ps = 0.f; int pidx = 0;
    if (valid) {
        ps   = unfkey((unsigned)(ck >> 32));
        pidx = (int)(0xFFFFFFFFu - (unsigned)(ck & 0xFFFFFFFFull));
    }
    float skey = valid ? ps : -INFINITY;
    s_key[tid] = skey;
    __syncthreads();

    int rank = 0;
    for (int j = 0; j < NCELLS; j++) {
        float o = s_key[j];
        rank += (o > skey) || (o == skey && j < tid);
    }

    out[rank * 3 + 0] = valid ? (float)(pidx % W) : -1.f;
    out[rank * 3 + 1] = valid ? (float)(pidx / W) : -1.f;
    out[rank * 3 + 2] = valid ? ps : -1.f;

    if (tid == 0) {
        unsigned long long mk = atomicOr(&d_minkey, 0ull);
        unsigned bidx = (unsigned)(mk & 0xFFFFFFFFull);
        out[NCELLS * 3 + 0] = (float)(bidx % (unsigned)W);   // bg col (x)
        out[NCELLS * 3 + 1] = (float)(bidx / (unsigned)W);   // bg row (y)
    }
}

// ---------------- launch ----------------
extern "C" void kernel_launch(void* const* d_in, const int* in_sizes, int n_in,
                              void* d_out, int out_size) {
    int ie = 0, ir = 1, io = 2;
    for (int i = 0; i < n_in; i++) {
        if (in_sizes[i] == 2) io = i;
        else if (in_sizes[i] == EMBC) ir = i;
        else ie = i;
    }
    const float* emb = (const float*)d_in[ie];
    const float* ref = (const float*)d_in[ir];
    const int*   ori = (const int*)d_in[io];
    float* out = (float*)d_out;

    k_sim <<<32,   128>>>(emb, ref);
    k_prep<<<2304, 256>>>(ori);
    k_scan<<<SCAN_GRID, 256>>>(ori, out);
}

// round 3
// speedup vs baseline: 2.1478x; 2.1478x over previous
#include <cuda_runtime.h>
#include <math.h>

#define FEAT   64
#define EMBC   256
#define IMGSZ  1024
#define NCELLS 256
#define THRESH 0.65f

// ---------------- device scratch (no allocations allowed) ----------------
__device__ float d_sim[FEAT * FEAT];
__device__ float d_P[1024 * 1024];           // cropped intermediate (ph x pw)
__device__ float4 d_xtab[4096];              // scan x-taps: {i0 (bitcast), w0, w1, 0}
__device__ float4 d_xt1[1024];               // prep x-taps into 64-wide sim rows
__device__ unsigned long long d_minkey;      // global argmin key
__device__ unsigned long long d_cellkey[NCELLS];

// ---------------- ordered-float key helpers ----------------
__device__ __forceinline__ unsigned fkey(float f) {
    unsigned u = __float_as_uint(f);
    return (u >> 31) ? ~u : (u | 0x80000000u);   // monotone: smaller float -> smaller key
}
__device__ __forceinline__ float unfkey(unsigned k) {
    return (k & 0x80000000u) ? __uint_as_float(k & 0x7FFFFFFFu) : __uint_as_float(~k);
}

// ---------------- jax.image.resize (linear, antialias=False) fp-exact taps ----------------
struct Tap { int i0; float w0, w1; };

__device__ __forceinline__ float samplef(int o, float inv) {
    return __fsub_rn(__fmul_rn(__fadd_rn((float)o, 0.5f), inv), 0.5f);
}

__device__ __forceinline__ Tap make_tap(float s, int n) {
    Tap t;
    float fs = floorf(s);
    int i0 = (int)fs;
    if (i0 < 0)            { t.i0 = 0;     t.w0 = 1.f; t.w1 = 0.f; }
    else if (i0 >= n - 1)  { t.i0 = n - 2; t.w0 = 0.f; t.w1 = 1.f; }
    else {
        float w0  = __fsub_rn(1.0f, __fsub_rn(s, fs));
        float w1  = __fsub_rn(1.0f, __fsub_rn((float)(i0 + 1), s));
        float sum = __fadd_rn(w0, w1);
        if (sum != 1.0f) { w0 = __fdiv_rn(w0, sum); w1 = __fdiv_rn(w1, sum); }
        t.i0 = i0; t.w0 = w0; t.w1 = w1;
    }
    return t;
}

// ---------------- kernel 1: sim (8-way channel split) + tables + init ----------------
// Blocks 0..127: 32 pixels each, 8 channel-groups of 32 channels, smem reduce
// in FIXED order (deterministic). Blocks 128..143: tap tables + key init.
__global__ void __launch_bounds__(256) k_simtab(const float* __restrict__ emb,
                                                const float* __restrict__ ref,
                                                const int* __restrict__ ori) {
    int t = threadIdx.x;
    if (blockIdx.x < 128) {
        __shared__ float sref[EMBC];
        __shared__ float sdot[256];
        __shared__ float snrm[256];
        sref[t] = ref[t];
        __syncthreads();

        int px = t & 31;
        int q  = t >> 5;                      // channel group 0..7
        int p  = (blockIdx.x << 5) + px;      // feature pixel
        const float* e = emb + (q * 32) * (FEAT * FEAT) + p;
        const float* r = sref + q * 32;
        float dot = 0.f, nrm = 0.f;
        #pragma unroll
        for (int j = 0; j < 32; j++) {
            float v = e[j * (FEAT * FEAT)];   // coalesced, 32 independent loads
            dot = fmaf(r[j], v, dot);
            nrm = fmaf(v, v, nrm);
        }
        sdot[t] = dot; snrm[t] = nrm;
        __syncthreads();

        if (t < 32) {
            float D = sdot[t], N = snrm[t];
            #pragma unroll
            for (int q2 = 1; q2 < 8; q2++) {  // fixed sequential order
                D += sdot[t + (q2 << 5)];
                N += snrm[t + (q2 << 5)];
            }
            d_sim[(blockIdx.x << 5) + t] = D / sqrtf(N);
        }
    } else {
        int idx = (blockIdx.x - 128) * 256 + t;   // 0..4095
        if (idx == 0) d_minkey = ~0ull;
        if (idx < NCELLS) d_cellkey[idx] = 0ull;

        if (idx < 1024) {                         // prep x-taps (64 -> 1024, inv = 1/16)
            Tap tp = make_tap(samplef(idx, 0.0625f), FEAT);
            d_xt1[idx] = make_float4(__int_as_float(tp.i0), tp.w0, tp.w1, 0.f);
        }
        int H = ori[0], W = ori[1];
        int mx = max(H, W);
        double scale = (double)IMGSZ / (double)mx;
        int pw = (int)floor((double)W * scale + 0.5);
        float invx = (float)(1.0 / ((double)W / (double)pw));
        if (idx < W && idx < 4096) {              // scan x-taps (pw -> W)
            Tap tp = make_tap(samplef(idx, invx), pw);
            d_xtab[idx] = make_float4(__int_as_float(tp.i0), tp.w0, tp.w1, 0.f);
        }
    }
}

// ---------------- kernel 2: build P (resize 64->1024, cropped) — one block per row ----------------
__global__ void __launch_bounds__(256) k_prep(const int* __restrict__ ori) {
    int H = ori[0], W = ori[1];
    int mx = max(H, W);
    double scale = (double)IMGSZ / (double)mx;
    int ph = (int)floor((double)H * scale + 0.5);
    int pw = (int)floor((double)W * scale + 0.5);

    int yy = blockIdx.x;
    if (yy >= ph) return;
    int t = threadIdx.x;

    __shared__ float cyrow[FEAT];
    Tap ty = make_tap(samplef(yy, 0.0625f), FEAT);
    if (t < FEAT) {
        float a = d_sim[ty.i0 * FEAT + t];
        float c = d_sim[(ty.i0 + 1) * FEAT + t];
        cyrow[t] = fmaf(ty.w1, c, __fmul_rn(ty.w0, a));   // == c0 in the reference order
    }
    __syncthreads();

    float* rowP = d_P + yy * pw;
    for (int x = t; x < pw; x += 256) {
        float4 tp = d_xt1[x];
        int x0 = __float_as_int(tp.x);
        rowP[x] = fmaf(tp.z, cyrow[x0 + 1], __fmul_rn(tp.y, cyrow[x0]));
    }
}

// ---------------- kernel 3: scan all H x W pixels (R1-proven form) ----------------
__global__ void __launch_bounds__(256) k_scan(const int* __restrict__ ori) {
    int H = ori[0], W = ori[1];
    int mx = max(H, W);
    double scale = (double)IMGSZ / (double)mx;
    int ph = (int)floor((double)H * scale + 0.5);
    int pw = (int)floor((double)W * scale + 0.5);
    float invy = (float)(1.0 / ((double)H / (double)ph));
    float r64  = (float)(scale / 64.0);   // ratio / DOWNSIZING as fp32

    unsigned long long localkey = ~0ull;

    for (int y = blockIdx.x; y < H; y += gridDim.x) {
        Tap ty = make_tap(samplef(y, invy), ph);
        const float* __restrict__ R0 = d_P + ty.i0 * pw;
        const float* __restrict__ R1 = R0 + pw;
        float wy0 = ty.w0, wy1 = ty.w1;
        int gy16 = 16 * (int)floorf(__fmul_rn((float)y, r64));
        int base = y * W;

        float rbest = INFINITY; int rbidx = 0;
        for (int x = threadIdx.x; x < W; x += blockDim.x) {
            float4 tx = d_xtab[x];
            int x0 = __float_as_int(tx.x);
            float c0 = fmaf(wy1, R1[x0],     __fmul_rn(wy0, R0[x0]));
            float c1 = fmaf(wy1, R1[x0 + 1], __fmul_rn(wy0, R0[x0 + 1]));
            float v  = fmaf(tx.z, c1, __fmul_rn(tx.y, c0));

            if (v < rbest) { rbest = v; rbidx = base + x; }   // strict <: earliest idx

            if (v > THRESH) {  // rare; exact semantics preserved
                int cell = gy16 + (int)floorf(__fmul_rn((float)x, r64));
                unsigned long long ck = ((unsigned long long)fkey(v) << 32)
                                      | (unsigned)(0xFFFFFFFFu - (unsigned)(base + x));
                atomicMax(&d_cellkey[cell], ck);
            }
        }
        unsigned long long k = ((unsigned long long)fkey(rbest) << 32) | (unsigned)rbidx;
        localkey = min(localkey, k);
    }

    __shared__ unsigned long long sk[256];
    sk[threadIdx.x] = localkey;
    __syncthreads();
    for (int o = 128; o > 0; o >>= 1) {
        if (threadIdx.x < o) sk[threadIdx.x] = min(sk[threadIdx.x], sk[threadIdx.x + o]);
        __syncthreads();
    }
    if (threadIdx.x == 0) atomicMin(&d_minkey, sk[0]);
}

// ---------------- kernel 4: build points, stable-sort by score desc, write output ----------------
__global__ void k_final(const int* __restrict__ ori, float* __restrict__ out) {
    int W = ori[1];
    int t = threadIdx.x;
    __shared__ float s_key[NCELLS];

    unsigned long long ck = d_cellkey[t];
    bool valid = (ck != 0ull);
    float ps = 0.f; int pidx = 0;
    if (valid) {
        ps   = unfkey((unsigned)(ck >> 32));
        pidx = (int)(0xFFFFFFFFu - (unsigned)(ck & 0xFFFFFFFFull));
    }
    float skey = valid ? ps : -INFINITY;
    s_key[t] = skey;
    __syncthreads();

    int rank = 0;
    for (int j = 0; j < NCELLS; j++) {
        float o = s_key[j];
        rank += (o > skey) || (o == skey && j < t);
    }

    out[rank * 3 + 0] = valid ? (float)(pidx % W) : -1.f;
    out[rank * 3 + 1] = valid ? (float)(pidx / W) : -1.f;
    out[rank * 3 + 2] = valid ? ps : -1.f;

    if (t == 0) {
        unsigned long long mk = d_minkey;
        unsigned bidx = (unsigned)(mk & 0xFFFFFFFFull);
        out[NCELLS * 3 + 0] = (float)(bidx % (unsigned)W);   // bg col (x)
        out[NCELLS * 3 + 1] = (float)(bidx / (unsigned)W);   // bg row (y)
    }
}

// ---------------- launch ----------------
extern "C" void kernel_launch(void* const* d_in, const int* in_sizes, int n_in,
                              void* d_out, int out_size) {
    int ie = 0, ir = 1, io = 2;
    for (int i = 0; i < n_in; i++) {
        if (in_sizes[i] == 2) io = i;
        else if (in_sizes[i] == EMBC) ir = i;
        else ie = i;
    }
    const float* emb = (const float*)d_in[ie];
    const float* ref = (const float*)d_in[ir];
    const int*   ori = (const int*)d_in[io];
    float* out = (float*)d_out;

    k_simtab<<<144,  256>>>(emb, ref, ori);
    k_prep  <<<1024, 256>>>(ori);
    k_scan  <<<2160, 256>>>(ori);
    k_final <<<1,    256>>>(ori, out);
}

// round 4
// speedup vs baseline: 2.2441x; 1.0448x over previous
#include <cuda_runtime.h>
#include <math.h>

#define FEAT   64
#define EMBC   256
#define IMGSZ  1024
#define NCELLS 256
#define THRESH 0.65f

// ---------------- device scratch (no allocations allowed) ----------------
__device__ float d_sim[FEAT * FEAT];
__device__ float d_P[1024 * 1024];           // cropped intermediate (ph x pw)
__device__ float4 d_xtab[4096];              // scan x-taps: {i0 (bitcast), w0, w1, 0}
__device__ float4 d_xt1[1024];               // prep x-taps into 64-wide sim rows
__device__ unsigned long long d_minkey;      // global argmin key
__device__ unsigned long long d_cellkey[NCELLS];

// ---------------- ordered-float key helpers ----------------
__device__ __forceinline__ unsigned fkey(float f) {
    unsigned u = __float_as_uint(f);
    return (u >> 31) ? ~u : (u | 0x80000000u);   // monotone: smaller float -> smaller key
}
__device__ __forceinline__ float unfkey(unsigned k) {
    return (k & 0x80000000u) ? __uint_as_float(k & 0x7FFFFFFFu) : __uint_as_float(~k);
}

// ---------------- jax.image.resize (linear, antialias=False) fp-exact taps ----------------
struct Tap { int i0; float w0, w1; };

__device__ __forceinline__ float samplef(int o, float inv) {
    return __fsub_rn(__fmul_rn(__fadd_rn((float)o, 0.5f), inv), 0.5f);
}

__device__ __forceinline__ Tap make_tap(float s, int n) {
    Tap t;
    float fs = floorf(s);
    int i0 = (int)fs;
    if (i0 < 0)            { t.i0 = 0;     t.w0 = 1.f; t.w1 = 0.f; }
    else if (i0 >= n - 1)  { t.i0 = n - 2; t.w0 = 0.f; t.w1 = 1.f; }
    else {
        float w0  = __fsub_rn(1.0f, __fsub_rn(s, fs));
        float w1  = __fsub_rn(1.0f, __fsub_rn((float)(i0 + 1), s));
        float sum = __fadd_rn(w0, w1);
        if (sum != 1.0f) { w0 = __fdiv_rn(w0, sum); w1 = __fdiv_rn(w1, sum); }
        t.i0 = i0; t.w0 = w0; t.w1 = w1;
    }
    return t;
}

// ---------------- kernel 1: sim (8-way channel split) + tables + init ----------------
__global__ void __launch_bounds__(256) k_simtab(const float* __restrict__ emb,
                                                const float* __restrict__ ref,
                                                const int* __restrict__ ori) {
    int t = threadIdx.x;
    if (blockIdx.x < 128) {
        __shared__ float sref[EMBC];
        __shared__ float sdot[256];
        __shared__ float snrm[256];
        sref[t] = ref[t];
        __syncthreads();

        int px = t & 31;
        int q  = t >> 5;                      // channel group 0..7
        int p  = (blockIdx.x << 5) + px;      // feature pixel
        const float* e = emb + (q * 32) * (FEAT * FEAT) + p;
        const float* r = sref + q * 32;
        float dot = 0.f, nrm = 0.f;
        #pragma unroll
        for (int j = 0; j < 32; j++) {
            float v = e[j * (FEAT * FEAT)];   // coalesced, 32 independent loads
            dot = fmaf(r[j], v, dot);
            nrm = fmaf(v, v, nrm);
        }
        sdot[t] = dot; snrm[t] = nrm;
        __syncthreads();

        if (t < 32) {
            float D = sdot[t], N = snrm[t];
            #pragma unroll
            for (int q2 = 1; q2 < 8; q2++) {  // fixed sequential order (deterministic)
                D += sdot[t + (q2 << 5)];
                N += snrm[t + (q2 << 5)];
            }
            d_sim[(blockIdx.x << 5) + t] = D / sqrtf(N);
        }
    } else {
        int idx = (blockIdx.x - 128) * 256 + t;   // 0..4095
        if (idx == 0) d_minkey = ~0ull;
        if (idx < NCELLS) d_cellkey[idx] = 0ull;

        if (idx < 1024) {                         // prep x-taps (64 -> 1024, inv = 1/16)
            Tap tp = make_tap(samplef(idx, 0.0625f), FEAT);
            d_xt1[idx] = make_float4(__int_as_float(tp.i0), tp.w0, tp.w1, 0.f);
        }
        int H = ori[0], W = ori[1];
        int mx = max(H, W);
        double scale = (double)IMGSZ / (double)mx;
        int pw = (int)floor((double)W * scale + 0.5);
        float invx = (float)(1.0 / ((double)W / (double)pw));
        if (idx < W && idx < 4096) {              // scan x-taps (pw -> W)
            Tap tp = make_tap(samplef(idx, invx), pw);
            d_xtab[idx] = make_float4(__int_as_float(tp.i0), tp.w0, tp.w1, 0.f);
        }
    }
}

// ---------------- kernel 2: build P (resize 64->1024, cropped) — one block per row ----------------
__global__ void __launch_bounds__(256) k_prep(const int* __restrict__ ori) {
    int H = ori[0], W = ori[1];
    int mx = max(H, W);
    double scale = (double)IMGSZ / (double)mx;
    int ph = (int)floor((double)H * scale + 0.5);
    int pw = (int)floor((double)W * scale + 0.5);

    int yy = blockIdx.x;
    if (yy >= ph) return;
    int t = threadIdx.x;

    __shared__ float cyrow[FEAT];
    Tap ty = make_tap(samplef(yy, 0.0625f), FEAT);
    if (t < FEAT) {
        float a = d_sim[ty.i0 * FEAT + t];
        float c = d_sim[(ty.i0 + 1) * FEAT + t];
        cyrow[t] = fmaf(ty.w1, c, __fmul_rn(ty.w0, a));
    }
    __syncthreads();

    float* rowP = d_P + yy * pw;
    for (int x = t; x < pw; x += 256) {
        float4 tp = d_xt1[x];
        int x0 = __float_as_int(tp.x);
        rowP[x] = fmaf(tp.z, cyrow[x0 + 1], __fmul_rn(tp.y, cyrow[x0]));
    }
}

// ---------------- kernel 3: scan all H x W pixels, 2 pixels per iteration for ILP ----------------
__global__ void __launch_bounds__(256) k_scan(const int* __restrict__ ori) {
    int H = ori[0], W = ori[1];
    int mx = max(H, W);
    double scale = (double)IMGSZ / (double)mx;
    int ph = (int)floor((double)H * scale + 0.5);
    int pw = (int)floor((double)W * scale + 0.5);
    float invy = (float)(1.0 / ((double)H / (double)ph));
    float r64  = (float)(scale / 64.0);   // ratio / DOWNSIZING as fp32

    unsigned long long localkey = ~0ull;

    for (int y = blockIdx.x; y < H; y += gridDim.x) {
        Tap ty = make_tap(samplef(y, invy), ph);
        const float* __restrict__ R0 = d_P + ty.i0 * pw;
        const float* __restrict__ R1 = R0 + pw;
        float wy0 = ty.w0, wy1 = ty.w1;
        int gy16 = 16 * (int)floorf(__fmul_rn((float)y, r64));
        int base = y * W;

        float rbest = INFINITY; int rbidx = 0;
        for (int x = threadIdx.x; x < W; x += 512) {
            int xb = x + 256;
            bool has2 = (xb < W);

            // issue both pixels' full load chains before consuming (ILP x2)
            float4 ta = d_xtab[x];
            float4 tb = has2 ? d_xtab[xb] : ta;
            int xa0 = __float_as_int(ta.x);
            int xb0 = __float_as_int(tb.x);
            float a00 = R0[xa0], a01 = R0[xa0 + 1], a10 = R1[xa0], a11 = R1[xa0 + 1];
            float b00 = R0[xb0], b01 = R0[xb0 + 1], b10 = R1[xb0], b11 = R1[xb0 + 1];

            float ca0 = fmaf(wy1, a10, __fmul_rn(wy0, a00));
            float ca1 = fmaf(wy1, a11, __fmul_rn(wy0, a01));
            float va  = fmaf(ta.z, ca1, __fmul_rn(ta.y, ca0));

            float cb0 = fmaf(wy1, b10, __fmul_rn(wy0, b00));
            float cb1 = fmaf(wy1, b11, __fmul_rn(wy0, b01));
            float vb  = fmaf(tb.z, cb1, __fmul_rn(tb.y, cb0));

            if (va < rbest) { rbest = va; rbidx = base + x; }     // x first (lower idx)
            if (has2 && vb < rbest) { rbest = vb; rbidx = base + xb; }

            if (va > THRESH) {
                int cell = gy16 + (int)floorf(__fmul_rn((float)x, r64));
                unsigned long long ck = ((unsigned long long)fkey(va) << 32)
                                      | (unsigned)(0xFFFFFFFFu - (unsigned)(base + x));
                atomicMax(&d_cellkey[cell], ck);
            }
            if (has2 && vb > THRESH) {
                int cell = gy16 + (int)floorf(__fmul_rn((float)xb, r64));
                unsigned long long ck = ((unsigned long long)fkey(vb) << 32)
                                      | (unsigned)(0xFFFFFFFFu - (unsigned)(base + xb));
                atomicMax(&d_cellkey[cell], ck);
            }
        }
        unsigned long long k = ((unsigned long long)fkey(rbest) << 32) | (unsigned)rbidx;
        localkey = min(localkey, k);
    }

    __shared__ unsigned long long sk[256];
    sk[threadIdx.x] = localkey;
    __syncthreads();
    for (int o = 128; o > 0; o >>= 1) {
        if (threadIdx.x < o) sk[threadIdx.x] = min(sk[threadIdx.x], sk[threadIdx.x + o]);
        __syncthreads();
    }
    if (threadIdx.x == 0) atomicMin(&d_minkey, sk[0]);
}

// ---------------- kernel 4: build points, stable-sort by score desc, write output ----------------
__global__ void __launch_bounds__(256) k_final(const int* __restrict__ ori,
                                               float* __restrict__ out) {
    int W = ori[1];
    int t = threadIdx.x;
    __shared__ float s_key[NCELLS];

    unsigned long long ck = d_cellkey[t];
    bool valid = (ck != 0ull);
    float ps = 0.f; int pidx = 0;
    if (valid) {
        ps   = unfkey((unsigned)(ck >> 32));
        pidx = (int)(0xFFFFFFFFu - (unsigned)(ck & 0xFFFFFFFFull));
    }
    float skey = valid ? ps : -INFINITY;
    s_key[t] = skey;
    __syncthreads();

    // stable descending rank; unrolled x8 so LDS latency pipelines
    int rank = 0;
    #pragma unroll 8
    for (int j = 0; j < NCELLS; j++) {
        float o = s_key[j];
        rank += (o > skey) || (o == skey && j < t);
    }

    out[rank * 3 + 0] = valid ? (float)(pidx % W) : -1.f;
    out[rank * 3 + 1] = valid ? (float)(pidx / W) : -1.f;
    out[rank * 3 + 2] = valid ? ps : -1.f;

    if (t == 0) {
        unsigned long long mk = d_minkey;
        unsigned bidx = (unsigned)(mk & 0xFFFFFFFFull);
        out[NCELLS * 3 + 0] = (float)(bidx % (unsigned)W);   // bg col (x)
        out[NCELLS * 3 + 1] = (float)(bidx / (unsigned)W);   // bg row (y)
    }
}

// ---------------- launch ----------------
extern "C" void kernel_launch(void* const* d_in, const int* in_sizes, int n_in,
                              void* d_out, int out_size) {
    int ie = 0, ir = 1, io = 2;
    for (int i = 0; i < n_in; i++) {
        if (in_sizes[i] == 2) io = i;
        else if (in_sizes[i] == EMBC) ir = i;
        else ie = i;
    }
    const float* emb = (const float*)d_in[ie];
    const float* ref = (const float*)d_in[ir];
    const int*   ori = (const int*)d_in[io];
    float* out = (float*)d_out;

    k_simtab<<<144,  256>>>(emb, ref, ori);
    k_prep  <<<1024, 256>>>(ori);
    k_scan  <<<2160, 256>>>(ori);
    k_final <<<1,    256>>>(ori, out);
}

// round 5
// speedup vs baseline: 3.4481x; 1.5366x over previous
#include <cuda_runtime.h>
#include <math.h>

#define FEAT   64
#define EMBC   256
#define IMGSZ  1024
#define NCELLS 256
#define THRESH 0.65f
#define SCAN_BX 15
#define SCAN_BY 48

// ---------------- device scratch (no allocations allowed) ----------------
__device__ float d_sim[FEAT * FEAT];
__device__ float d_P[1024 * 1024];           // cropped intermediate (ph x pw)
__device__ float4 d_xtab[4096];              // scan x-taps: {i0 (bits), w0, w1, gx16? no:0}
__device__ float4 d_ytab[4096];              // scan y-taps: {i0 (bits), w0, w1, gy16 (bits)}
__device__ float4 d_xt1[1024];               // prep x-taps into 64-wide sim rows
__device__ unsigned long long d_minkey;      // global argmin key
__device__ unsigned long long d_cellkey[NCELLS];
__device__ int d_counter;

// ---------------- ordered-float key helpers ----------------
__device__ __forceinline__ unsigned fkey(float f) {
    unsigned u = __float_as_uint(f);
    return (u >> 31) ? ~u : (u | 0x80000000u);   // monotone: smaller float -> smaller key
}
__device__ __forceinline__ float unfkey(unsigned k) {
    return (k & 0x80000000u) ? __uint_as_float(k & 0x7FFFFFFFu) : __uint_as_float(~k);
}

// ---------------- jax.image.resize (linear, antialias=False) fp-exact taps ----------------
struct Tap { int i0; float w0, w1; };

__device__ __forceinline__ float samplef(int o, float inv) {
    return __fsub_rn(__fmul_rn(__fadd_rn((float)o, 0.5f), inv), 0.5f);
}

__device__ __forceinline__ Tap make_tap(float s, int n) {
    Tap t;
    float fs = floorf(s);
    int i0 = (int)fs;
    if (i0 < 0)            { t.i0 = 0;     t.w0 = 1.f; t.w1 = 0.f; }
    else if (i0 >= n - 1)  { t.i0 = n - 2; t.w0 = 0.f; t.w1 = 1.f; }
    else {
        float w0  = __fsub_rn(1.0f, __fsub_rn(s, fs));
        float w1  = __fsub_rn(1.0f, __fsub_rn((float)(i0 + 1), s));
        float sum = __fadd_rn(w0, w1);
        if (sum != 1.0f) { w0 = __fdiv_rn(w0, sum); w1 = __fdiv_rn(w1, sum); }
        t.i0 = i0; t.w0 = w0; t.w1 = w1;
    }
    return t;
}

// ---------------- kernel 1: sim (8-way channel split) + all tap tables + init ----------------
__global__ void __launch_bounds__(256) k_simtab(const float* __restrict__ emb,
                                                const float* __restrict__ ref,
                                                const int* __restrict__ ori) {
    int t = threadIdx.x;
    if (blockIdx.x < 128) {
        __shared__ float sref[EMBC];
        __shared__ float sdot[256];
        __shared__ float snrm[256];
        sref[t] = ref[t];
        __syncthreads();

        int px = t & 31;
        int q  = t >> 5;                      // channel group 0..7
        int p  = (blockIdx.x << 5) + px;      // feature pixel
        const float* e = emb + (q * 32) * (FEAT * FEAT) + p;
        const float* r = sref + q * 32;
        float dot = 0.f, nrm = 0.f;
        #pragma unroll
        for (int j = 0; j < 32; j++) {
            float v = e[j * (FEAT * FEAT)];   // coalesced, 32 independent loads
            dot = fmaf(r[j], v, dot);
            nrm = fmaf(v, v, nrm);
        }
        sdot[t] = dot; snrm[t] = nrm;
        __syncthreads();

        if (t < 32) {
            float D = sdot[t], N = snrm[t];
            #pragma unroll
            for (int q2 = 1; q2 < 8; q2++) {  // fixed sequential order (deterministic)
                D += sdot[t + (q2 << 5)];
                N += snrm[t + (q2 << 5)];
            }
            d_sim[(blockIdx.x << 5) + t] = D / sqrtf(N);
        }
    } else {
        int idx = (blockIdx.x - 128) * 256 + t;   // 0..4095
        if (idx == 0) { d_minkey = ~0ull; d_counter = 0; }
        if (idx < NCELLS) d_cellkey[idx] = 0ull;

        if (idx < 1024) {                         // prep x-taps (64 -> 1024, inv = 1/16)
            Tap tp = make_tap(samplef(idx, 0.0625f), FEAT);
            d_xt1[idx] = make_float4(__int_as_float(tp.i0), tp.w0, tp.w1, 0.f);
        }
        int H = ori[0], W = ori[1];
        int mx = max(H, W);
        double scale = (double)IMGSZ / (double)mx;
        int ph = (int)floor((double)H * scale + 0.5);
        int pw = (int)floor((double)W * scale + 0.5);
        float invx = (float)(1.0 / ((double)W / (double)pw));
        float invy = (float)(1.0 / ((double)H / (double)ph));
        float r64  = (float)(scale / 64.0);
        if (idx < W) {                            // scan x-taps (pw -> W)
            Tap tp = make_tap(samplef(idx, invx), pw);
            d_xtab[idx] = make_float4(__int_as_float(tp.i0), tp.w0, tp.w1, 0.f);
        }
        if (idx < H) {                            // scan y-taps (ph -> H) + gy16
            Tap tp = make_tap(samplef(idx, invy), ph);
            int gy16 = 16 * (int)floorf(__fmul_rn((float)idx, r64));
            d_ytab[idx] = make_float4(__int_as_float(tp.i0), tp.w0, tp.w1,
                                      __int_as_float(gy16));
        }
    }
}

// ---------------- kernel 2: build P (resize 64->1024, cropped) — one block per row ----------------
__global__ void __launch_bounds__(256) k_prep(const int* __restrict__ ori) {
    int H = ori[0], W = ori[1];
    int mx = max(H, W);
    double scale = (double)IMGSZ / (double)mx;
    int ph = (int)floor((double)H * scale + 0.5);
    int pw = (int)floor((double)W * scale + 0.5);

    int yy = blockIdx.x;
    if (yy >= ph) return;
    int t = threadIdx.x;

    __shared__ float cyrow[FEAT];
    Tap ty = make_tap(samplef(yy, 0.0625f), FEAT);
    if (t < FEAT) {
        float a = d_sim[ty.i0 * FEAT + t];
        float c = d_sim[(ty.i0 + 1) * FEAT + t];
        cyrow[t] = fmaf(ty.w1, c, __fmul_rn(ty.w0, a));
    }
    __syncthreads();

    float* rowP = d_P + yy * pw;
    for (int x = t; x < pw; x += 256) {
        float4 tp = d_xt1[x];
        int x0 = __float_as_int(tp.x);
        rowP[x] = fmaf(tp.z, cyrow[x0 + 1], __fmul_rn(tp.y, cyrow[x0]));
    }
}

// ---------------- kernel 3: column-major scan + fused finalize ----------------
// Thread = one output column x, walking a y-strip. x-tap loaded once; the 4 P taps
// reload only when ty.i0 changes (~every 3.75 rows). Arithmetic identical to before.
__global__ void __launch_bounds__(256) k_scan(const int* __restrict__ ori,
                                              float* __restrict__ out) {
    int H = ori[0], W = ori[1];
    int mx = max(H, W);
    double scale = (double)IMGSZ / (double)mx;
    int pw = (int)floor((double)W * scale + 0.5);
    float r64  = (float)(scale / 64.0);

    int x = blockIdx.x * 256 + threadIdx.x;
    int nby = gridDim.y;
    int ch = (H + nby - 1) / nby;
    int ys = blockIdx.y * ch;
    int ye = min(H, ys + ch);

    unsigned long long localkey = ~0ull;

    if (x < W && ys < H) {
        float4 tx = d_xtab[x];
        int   x0  = __float_as_int(tx.x);
        float wx0 = tx.y, wx1 = tx.z;
        int   gx  = (int)floorf(__fmul_rn((float)x, r64));

        int cur = -1;
        float a0 = 0.f, a1 = 0.f, b0 = 0.f, b1 = 0.f;
        float rbest = INFINITY; int rbidx = 0;

        for (int y = ys; y < ye; y++) {
            float4 ty = d_ytab[y];               // uniform across warp, L1-hot
            int i0 = __float_as_int(ty.x);
            if (i0 != cur) {                     // warp-uniform reload (~every 3.75 y)
                const float* __restrict__ R = d_P + i0 * pw;
                a0 = R[x0]; a1 = R[x0 + 1];
                b0 = R[pw + x0]; b1 = R[pw + x0 + 1];
                cur = i0;
            }
            float c0 = fmaf(ty.z, b0, __fmul_rn(ty.y, a0));
            float c1 = fmaf(ty.z, b1, __fmul_rn(ty.y, a1));
            float v  = fmaf(wx1, c1, __fmul_rn(wx0, c0));

            if (v < rbest) { rbest = v; rbidx = y * W + x; }   // idx monotone in y

            if (v > THRESH) {                    // rare; exact semantics preserved
                int cell = __float_as_int(ty.w) + gx;
                unsigned long long ck = ((unsigned long long)fkey(v) << 32)
                                      | (unsigned)(0xFFFFFFFFu - (unsigned)(y * W + x));
                atomicMax(&d_cellkey[cell], ck);
            }
        }
        localkey = ((unsigned long long)fkey(rbest) << 32) | (unsigned)rbidx;
    }

    // block argmin reduction
    __shared__ unsigned long long sk[256];
    __shared__ int s_last;
    int t = threadIdx.x;
    sk[t] = localkey;
    __syncthreads();
    for (int o = 128; o > 0; o >>= 1) {
        if (t < o) sk[t] = min(sk[t], sk[t + o]);
        __syncthreads();
    }
    if (t == 0) {
        atomicMin(&d_minkey, sk[0]);
        __threadfence();
        s_last = (atomicAdd(&d_counter, 1) == (int)(gridDim.x * gridDim.y) - 1);
    }
    __syncthreads();
    if (!s_last) return;

    // ---- last block: finalize ----
    __shared__ float s_key[NCELLS];
    unsigned long long ck = atomicOr(&d_cellkey[t], 0ull);    // coherent read
    bool valid = (ck != 0ull);
    float ps = 0.f; int pidx = 0;
    if (valid) {
        ps   = unfkey((unsigned)(ck >> 32));
        pidx = (int)(0xFFFFFFFFu - (unsigned)(ck & 0xFFFFFFFFull));
    }
    float skey = valid ? ps : -INFINITY;
    s_key[t] = skey;
    __syncthreads();

    int rank = 0;
    #pragma unroll 8
    for (int j = 0; j < NCELLS; j++) {
        float o = s_key[j];
        rank += (o > skey) || (o == skey && j < t);
    }

    out[rank * 3 + 0] = valid ? (float)(pidx % W) : -1.f;
    out[rank * 3 + 1] = valid ? (float)(pidx / W) : -1.f;
    out[rank * 3 + 2] = valid ? ps : -1.f;

    if (t == 0) {
        unsigned long long mk = atomicOr(&d_minkey, 0ull);
        unsigned bidx = (unsigned)(mk & 0xFFFFFFFFull);
        out[NCELLS * 3 + 0] = (float)(bidx % (unsigned)W);   // bg col (x)
        out[NCELLS * 3 + 1] = (float)(bidx / (unsigned)W);   // bg row (y)
    }
}

// ---------------- launch ----------------
extern "C" void kernel_launch(void* const* d_in, const int* in_sizes, int n_in,
                              void* d_out, int out_size) {
    int ie = 0, ir = 1, io = 2;
    for (int i = 0; i < n_in; i++) {
        if (in_sizes[i] == 2) io = i;
        else if (in_sizes[i] == EMBC) ir = i;
        else ie = i;
    }
    const float* emb = (const float*)d_in[ie];
    const float* ref = (const float*)d_in[ir];
    const int*   ori = (const int*)d_in[io];
    float* out = (float*)d_out;

    k_simtab<<<144,  256>>>(emb, ref, ori);
    k_prep  <<<1024, 256>>>(ori);
    k_scan  <<<dim3(SCAN_BX, SCAN_BY), 256>>>(ori, out);
}

// round 7
// speedup vs baseline: 4.4463x; 1.2895x over previous
#include <cuda_runtime.h>
#include <math.h>

#define FEAT   64
#define EMBC   256
#define IMGSZ  1024
#define NCELLS 256
#define THRESH 0.65f
#define SCAN_BX 15
#define SCAN_BY 48
#define TILE_R  16
#define TILE_C  80

// ---------------- device scratch (no allocations allowed) ----------------
__device__ float d_sim[FEAT * FEAT];
__device__ float4 d_xtab[4096];              // scan x-taps: {i0 (bits), w0, w1, 0}
__device__ float4 d_ytab[4096];              // scan y-taps: {i0 (bits), w0, w1, gy16 (bits)}
__device__ float4 d_xt1[1024];               // 64->1024 taps (used for P rows AND cols)
__device__ unsigned long long d_minkey;      // global argmin key
__device__ unsigned long long d_cellkey[NCELLS];
__device__ int d_counter;

// ---------------- ordered-float key helpers ----------------
__device__ __forceinline__ unsigned fkey(float f) {
    unsigned u = __float_as_uint(f);
    return (u >> 31) ? ~u : (u | 0x80000000u);   // monotone: smaller float -> smaller key
}
__device__ __forceinline__ float unfkey(unsigned k) {
    return (k & 0x80000000u) ? __uint_as_float(k & 0x7FFFFFFFu) : __uint_as_float(~k);
}

// ---------------- jax.image.resize (linear, antialias=False) fp-exact taps ----------------
struct Tap { int i0; float w0, w1; };

__device__ __forceinline__ float samplef(int o, float inv) {
    return __fsub_rn(__fmul_rn(__fadd_rn((float)o, 0.5f), inv), 0.5f);
}

__device__ __forceinline__ Tap make_tap(float s, int n) {
    Tap t;
    float fs = floorf(s);
    int i0 = (int)fs;
    if (i0 < 0)            { t.i0 = 0;     t.w0 = 1.f; t.w1 = 0.f; }
    else if (i0 >= n - 1)  { t.i0 = n - 2; t.w0 = 0.f; t.w1 = 1.f; }
    else {
        float w0  = __fsub_rn(1.0f, __fsub_rn(s, fs));
        float w1  = __fsub_rn(1.0f, __fsub_rn((float)(i0 + 1), s));
        float sum = __fadd_rn(w0, w1);
        if (sum != 1.0f) { w0 = __fdiv_rn(w0, sum); w1 = __fdiv_rn(w1, sum); }
        t.i0 = i0; t.w0 = w0; t.w1 = w1;
    }
    return t;
}

// ---------------- kernel 1: sim (8-way channel split) + all tap tables + init ----------------
__global__ void __launch_bounds__(256) k_simtab(const float* __restrict__ emb,
                                                const float* __restrict__ ref,
                                                const int* __restrict__ ori) {
    int t = threadIdx.x;
    if (blockIdx.x < 128) {
        __shared__ float sref[EMBC];
        __shared__ float sdot[256];
        __shared__ float snrm[256];
        sref[t] = ref[t];
        __syncthreads();

        int px = t & 31;
        int q  = t >> 5;                      // channel group 0..7
        int p  = (blockIdx.x << 5) + px;      // feature pixel
        const float* e = emb + (q * 32) * (FEAT * FEAT) + p;
        const float* r = sref + q * 32;
        float dot = 0.f, nrm = 0.f;
        #pragma unroll
        for (int j = 0; j < 32; j++) {
            float v = e[j * (FEAT * FEAT)];   // coalesced, 32 independent loads
            dot = fmaf(r[j], v, dot);
            nrm = fmaf(v, v, nrm);
        }
        sdot[t] = dot; snrm[t] = nrm;
        __syncthreads();

        if (t < 32) {
            float D = sdot[t], N = snrm[t];
            #pragma unroll
            for (int q2 = 1; q2 < 8; q2++) {  // fixed sequential order (deterministic)
                D += sdot[t + (q2 << 5)];
                N += snrm[t + (q2 << 5)];
            }
            d_sim[(blockIdx.x << 5) + t] = D / sqrtf(N);
        }
    } else {
        int idx = (blockIdx.x - 128) * 256 + t;   // 0..4095
        if (idx == 0) { d_minkey = ~0ull; d_counter = 0; }
        if (idx < NCELLS) d_cellkey[idx] = 0ull;

        if (idx < 1024) {                         // 64 -> 1024 taps (P rows and cols)
            Tap tp = make_tap(samplef(idx, 0.0625f), FEAT);
            d_xt1[idx] = make_float4(__int_as_float(tp.i0), tp.w0, tp.w1, 0.f);
        }
        int H = ori[0], W = ori[1];
        int mx = max(H, W);
        double scale = (double)IMGSZ / (double)mx;
        int ph = (int)floor((double)H * scale + 0.5);
        int pw = (int)floor((double)W * scale + 0.5);
        float invx = (float)(1.0 / ((double)W / (double)pw));
        float invy = (float)(1.0 / ((double)H / (double)ph));
        float r64  = (float)(scale / 64.0);
        if (idx < W) {                            // scan x-taps (pw -> W)
            Tap tp = make_tap(samplef(idx, invx), pw);
            d_xtab[idx] = make_float4(__int_as_float(tp.i0), tp.w0, tp.w1, 0.f);
        }
        if (idx < H) {                            // scan y-taps (ph -> H) + gy16
            Tap tp = make_tap(samplef(idx, invy), ph);
            int gy16 = 16 * (int)floorf(__fmul_rn((float)idx, r64));
            d_ytab[idx] = make_float4(__int_as_float(tp.i0), tp.w0, tp.w1,
                                      __int_as_float(gy16));
        }
    }
}

// ---------------- kernel 2: fused P-tile (smem) + column-major scan + finalize ----------------
__global__ void __launch_bounds__(256) k_scan(const int* __restrict__ ori,
                                              float* __restrict__ out) {
    int H = ori[0], W = ori[1];
    int mx = max(H, W);
    double scale = (double)IMGSZ / (double)mx;
    float r64  = (float)(scale / 64.0);

    __shared__ float tile[TILE_R][TILE_C];

    int t  = threadIdx.x;
    int xs = blockIdx.x * 256;
    int nby = gridDim.y;
    int chn = (H + nby - 1) / nby;
    int ys = blockIdx.y * chn;
    int ye = min(H, ys + chn);

    unsigned long long localkey = ~0ull;

    if (ys < H && xs < W) {
        int xe = min(xs + 256, W);
        // P-tile bounds this block needs (from the monotone tap tables)
        int pr0 = __float_as_int(d_ytab[ys].x);
        int pr1 = __float_as_int(d_ytab[ye - 1].x) + 1;
        int px0 = __float_as_int(d_xtab[xs].x);
        int px1 = __float_as_int(d_xtab[xe - 1].x) + 1;
        int NR = pr1 - pr0 + 1;            // <= 14
        int NC = px1 - px0 + 1;            // <= 70

        // build the local P tile (bit-identical expression to the old k_prep)
        for (int i = t; i < NR * NC; i += 256) {
            int r = i / NC, c = i - r * NC;
            float4 tyr = d_xt1[pr0 + r];
            float4 txc = d_xt1[px0 + c];
            int yi = __float_as_int(tyr.x);
            int xi = __float_as_int(txc.x);
            const float* s0 = d_sim + yi * FEAT;
            float cy0 = fmaf(tyr.z, s0[FEAT + xi],     __fmul_rn(tyr.y, s0[xi]));
            float cy1 = fmaf(tyr.z, s0[FEAT + xi + 1], __fmul_rn(tyr.y, s0[xi + 1]));
            tile[r][c] = fmaf(txc.z, cy1, __fmul_rn(txc.y, cy0));
        }
        __syncthreads();

        int x = xs + t;
        if (x < W) {
            float4 tx = d_xtab[x];
            int   lx  = __float_as_int(tx.x) - px0;
            float wx0 = tx.y, wx1 = tx.z;
            int   gx  = (int)floorf(__fmul_rn((float)x, r64));

            int cur = -1;
            float a0 = 0.f, a1 = 0.f, b0 = 0.f, b1 = 0.f;
            float rbest = INFINITY; int rbidx = 0;

            for (int y = ys; y < ye; y++) {
                float4 ty = d_ytab[y];           // warp-uniform, L1-hot
                int r = __float_as_int(ty.x);
                if (r != cur) {                  // reload every ~3.75 rows
                    int lr = r - pr0;
                    a0 = tile[lr][lx]; a1 = tile[lr][lx + 1];
                    b0 = tile[lr + 1][lx]; b1 = tile[lr + 1][lx + 1];
                    cur = r;
                }
                float c0 = fmaf(ty.z, b0, __fmul_rn(ty.y, a0));
                float c1 = fmaf(ty.z, b1, __fmul_rn(ty.y, a1));
                float v  = fmaf(wx1, c1, __fmul_rn(wx0, c0));

                if (v < rbest) { rbest = v; rbidx = y * W + x; }   // idx monotone in y

                if (v > THRESH) {                // rare; exact semantics preserved
                    int cell = __float_as_int(ty.w) + gx;
                    unsigned long long ck = ((unsigned long long)fkey(v) << 32)
                                          | (unsigned)(0xFFFFFFFFu - (unsigned)(y * W + x));
                    atomicMax(&d_cellkey[cell], ck);
                }
            }
            localkey = ((unsigned long long)fkey(rbest) << 32) | (unsigned)rbidx;
        }
    }

    // block argmin reduction
    __shared__ unsigned long long sk[256];
    __shared__ int s_last;
    sk[t] = localkey;
    __syncthreads();
    for (int o = 128; o > 0; o >>= 1) {
        if (t < o) sk[t] = min(sk[t], sk[t + o]);
        __syncthreads();
    }
    if (t == 0) {
        atomicMin(&d_minkey, sk[0]);
        __threadfence();
        s_last = (atomicAdd(&d_counter, 1) == (int)(gridDim.x * gridDim.y) - 1);
    }
    __syncthreads();
    if (!s_last) return;

    // ---- last block: finalize ----
    __shared__ float s_key[NCELLS];
    unsigned long long ck = atomicOr(&d_cellkey[t], 0ull);    // coherent read
    bool valid = (ck != 0ull);
    float ps = 0.f; int pidx = 0;
    if (valid) {
        ps   = unfkey((unsigned)(ck >> 32));
        pidx = (int)(0xFFFFFFFFu - (unsigned)(ck & 0xFFFFFFFFull));
    }
    float skey = valid ? ps : -INFINITY;
    s_key[t] = skey;
    __syncthreads();

    int rank = 0;
    #pragma unroll 8
    for (int j = 0; j < NCELLS; j++) {
        float o = s_key[j];
        rank += (o > skey) || (o == skey && j < t);
    }

    out[rank * 3 + 0] = valid ? (float)(pidx % W) : -1.f;
    out[rank * 3 + 1] = valid ? (float)(pidx / W) : -1.f;
    out[rank * 3 + 2] = valid ? ps : -1.f;

    if (t == 0) {
        unsigned long long mk = atomicOr(&d_minkey, 0ull);
        unsigned bidx = (unsigned)(mk & 0xFFFFFFFFull);
        out[NCELLS * 3 + 0] = (float)(bidx % (unsigned)W);   // bg col (x)
        out[NCELLS * 3 + 1] = (float)(bidx / (unsigned)W);   // bg row (y)
    }
}

// ---------------- launch ----------------
extern "C" void kernel_launch(void* const* d_in, const int* in_sizes, int n_in,
                              void* d_out, int out_size) {
    int ie = 0, ir = 1, io = 2;
    for (int i = 0; i < n_in; i++) {
        if (in_sizes[i] == 2) io = i;
        else if (in_sizes[i] == EMBC) ir = i;
        else ie = i;
    }
    const float* emb = (const float*)d_in[ie];
    const float* ref = (const float*)d_in[ir];
    const int*   ori = (const int*)d_in[io];
    float* out = (float*)d_out;

    k_simtab<<<144, 256>>>(emb, ref, ori);
    k_scan  <<<dim3(SCAN_BX, SCAN_BY), 256>>>(ori, out);
}